// round 5
// baseline (speedup 1.0000x reference)
#include <cuda_runtime.h>
#include <cuda_bf16.h>

// Problem constants (match reference)
#define N_NODES 50000
#define N_EDGES 800000
#define N_FEAT  128
#define DIM     64
#define N_GRAPHS 512

// Scratch (device globals — no allocation allowed)
__device__ __align__(16) float g_h[N_NODES * DIM];      // gemm output (h1 then h2)
__device__ __align__(16) float g_agg1[N_NODES * DIM];   // relu(scatter conv1)
__device__ __align__(16) float g_agg2[N_NODES * DIM];   // scatter conv2
__device__ __align__(16) float g_pooled[N_GRAPHS * DIM];
__device__ __align__(16) float g_counts[N_GRAPHS];
// CSR (by destination)
__device__ int g_deg[N_NODES];
__device__ int g_off[N_NODES + 1];
__device__ int g_cursor[N_NODES];
__device__ int g_csr[N_EDGES];

// ---------------------------------------------------------------------------
// Zero small state (agg buffers are fully overwritten by gather — no zeroing)
// ---------------------------------------------------------------------------
__global__ void zero_kernel() {
    int i = blockIdx.x * blockDim.x + threadIdx.x;
    if (i < N_NODES) g_deg[i] = 0;
    if (i < N_GRAPHS * (DIM / 4))
        ((float4*)g_pooled)[i] = make_float4(0.f, 0.f, 0.f, 0.f);
    if (i < N_GRAPHS) g_counts[i] = 0.f;
}

// ---------------------------------------------------------------------------
// CSR build: histogram of dst, block-wide scan, atomic-bump fill
// ---------------------------------------------------------------------------
__global__ void hist_kernel(const int* __restrict__ ei) {
    int e = blockIdx.x * blockDim.x + threadIdx.x;
    if (e < N_EDGES) atomicAdd(&g_deg[ei[N_EDGES + e]], 1);
}

__global__ void scan_kernel() {
    __shared__ int part[1024];
    const int T = 1024;
    int tid = threadIdx.x;
    const int per = (N_NODES + T - 1) / T;   // 49
    int start = tid * per;
    int end = start + per; if (end > N_NODES) end = N_NODES;
    int s = 0;
    for (int i = start; i < end; i++) s += g_deg[i];
    part[tid] = s;
    __syncthreads();
    // Hillis-Steele inclusive scan
    for (int off = 1; off < T; off <<= 1) {
        int v = (tid >= off) ? part[tid - off] : 0;
        __syncthreads();
        part[tid] += v;
        __syncthreads();
    }
    int base = (tid == 0) ? 0 : part[tid - 1];
    for (int i = start; i < end; i++) {
        g_off[i] = base;
        g_cursor[i] = base;
        base += g_deg[i];
    }
    if (tid == T - 1) g_off[N_NODES] = base;  // = total (tail threads empty)
}

__global__ void fill_kernel(const int* __restrict__ ei) {
    int e = blockIdx.x * blockDim.x + threadIdx.x;
    if (e >= N_EDGES) return;
    int s = ei[e];
    int d = ei[N_EDGES + e];
    int p = atomicAdd(&g_cursor[d], 1);
    g_csr[p] = s;
}

// ---------------------------------------------------------------------------
// Register-blocked GEMM with packed fma.rn.f32x2 (Blackwell FFMA2).
// out g_h[N,64] = in[N,K] @ W[K,64].
// Block = 256 threads, 128 rows. Thread: 4 rows (q, q+32, q+64, q+96) x 8 cols.
// x staged in smem in K-chunks of 16 (stride 20 floats: 16B-aligned float4
// loads along k; per-instruction row addresses land in distinct banks).
// W fully staged; read as double2 = packed f32x2 operands (no repack movs).
// ---------------------------------------------------------------------------
typedef unsigned long long u64;

template<int K, bool FROM_X>
__global__ void gemm_kernel(const float4* __restrict__ xin,
                            const float* __restrict__ W) {
    constexpr int NC4 = K / 4;          // input row width in float4
    constexpr int CHUNK = 16;
    constexpr int NCHUNK = K / CHUNK;
    __shared__ __align__(16) float Ws[K * 64];
    __shared__ __align__(16) float xs[128 * 20];

    const float4* in = FROM_X ? xin : (const float4*)g_agg1;
    int tid = threadIdx.x;

    // stage W (K*64 floats = K*16 float4)
    for (int i = tid; i < K * 16; i += 256)
        ((float4*)Ws)[i] = ((const float4*)W)[i];

    int rowBase = blockIdx.x * 128;
    int q  = tid >> 3;      // 0..31 row slot
    int cg = tid & 7;       // 0..7 col group (8 cols)

    u64 acc[4][4];
    #pragma unroll
    for (int i = 0; i < 4; i++)
        #pragma unroll
        for (int j = 0; j < 4; j++) acc[i][j] = 0ULL;  // (+0.f, +0.f)

    for (int ch = 0; ch < NCHUNK; ch++) {
        __syncthreads();   // also covers Ws on first iteration
        // stage 128 rows x 16 k-floats = 512 float4
        for (int l = tid; l < 512; l += 256) {
            int r = l >> 2, j = l & 3;
            int gr = rowBase + r;
            float4 v = make_float4(0.f, 0.f, 0.f, 0.f);
            if (gr < N_NODES) v = in[gr * NC4 + ch * 4 + j];
            *(float4*)&xs[r * 20 + j * 4] = v;
        }
        __syncthreads();

        #pragma unroll
        for (int k4 = 0; k4 < CHUNK / 4; k4++) {
            float4 xv[4];
            #pragma unroll
            for (int i = 0; i < 4; i++)
                xv[i] = *(const float4*)&xs[(q + 32 * i) * 20 + k4 * 4];
            #pragma unroll
            for (int kk = 0; kk < 4; kk++) {
                int k = ch * CHUNK + k4 * 4 + kk;
                const double2* Wp = (const double2*)&Ws[k * 64 + cg * 8];
                double2 wA = Wp[0], wB = Wp[1];
                u64 w0 = __double_as_longlong(wA.x);
                u64 w1 = __double_as_longlong(wA.y);
                u64 w2 = __double_as_longlong(wB.x);
                u64 w3 = __double_as_longlong(wB.y);
                #pragma unroll
                for (int i = 0; i < 4; i++) {
                    float xf = (kk == 0) ? xv[i].x : (kk == 1) ? xv[i].y
                             : (kk == 2) ? xv[i].z : xv[i].w;
                    u64 xp;
                    asm("mov.b64 %0, {%1, %2};" : "=l"(xp) : "f"(xf), "f"(xf));
                    asm("fma.rn.f32x2 %0, %1, %2, %0;" : "+l"(acc[i][0]) : "l"(xp), "l"(w0));
                    asm("fma.rn.f32x2 %0, %1, %2, %0;" : "+l"(acc[i][1]) : "l"(xp), "l"(w1));
                    asm("fma.rn.f32x2 %0, %1, %2, %0;" : "+l"(acc[i][2]) : "l"(xp), "l"(w2));
                    asm("fma.rn.f32x2 %0, %1, %2, %0;" : "+l"(acc[i][3]) : "l"(xp), "l"(w3));
                }
            }
        }
    }

    #pragma unroll
    for (int i = 0; i < 4; i++) {
        int r = rowBase + q + 32 * i;
        if (r < N_NODES) {
            float4 o0, o1;
            asm("mov.b64 {%0, %1}, %2;" : "=f"(o0.x), "=f"(o0.y) : "l"(acc[i][0]));
            asm("mov.b64 {%0, %1}, %2;" : "=f"(o0.z), "=f"(o0.w) : "l"(acc[i][1]));
            asm("mov.b64 {%0, %1}, %2;" : "=f"(o1.x), "=f"(o1.y) : "l"(acc[i][2]));
            asm("mov.b64 {%0, %1}, %2;" : "=f"(o1.z), "=f"(o1.w) : "l"(acc[i][3]));
            ((float4*)g_h)[r * 16 + cg * 2]     = o0;
            ((float4*)g_h)[r * 16 + cg * 2 + 1] = o1;
        }
    }
}

// ---------------------------------------------------------------------------
// CSR gather: agg[n] = sum over incoming edges of h[src]. No atomics.
// 16 lanes (float4 columns) per node. phase 0: fuse ReLU into store (conv1).
// ---------------------------------------------------------------------------
__global__ void gather_kernel(int phase) {
    const float4* h = (const float4*)g_h;
    float4* agg = (float4*)(phase ? g_agg2 : g_agg1);
    int t = blockIdx.x * blockDim.x + threadIdx.x;
    if (t >= N_NODES * 16) return;
    int n = t >> 4, c = t & 15;
    int b = g_off[n], e = g_off[n + 1];
    float4 acc = make_float4(0.f, 0.f, 0.f, 0.f);
    int i = b;
    for (; i + 1 < e; i += 2) {        // 2-way unroll for MLP
        int s0 = g_csr[i], s1 = g_csr[i + 1];
        float4 v0 = h[s0 * 16 + c];
        float4 v1 = h[s1 * 16 + c];
        acc.x += v0.x; acc.y += v0.y; acc.z += v0.z; acc.w += v0.w;
        acc.x += v1.x; acc.y += v1.y; acc.z += v1.z; acc.w += v1.w;
    }
    if (i < e) {
        int s = g_csr[i];
        float4 v = h[s * 16 + c];
        acc.x += v.x; acc.y += v.y; acc.z += v.z; acc.w += v.w;
    }
    if (phase == 0) {
        acc.x = fmaxf(acc.x, 0.f); acc.y = fmaxf(acc.y, 0.f);
        acc.z = fmaxf(acc.z, 0.f); acc.w = fmaxf(acc.w, 0.f);
    }
    agg[n * 16 + c] = acc;
}

// ---------------------------------------------------------------------------
// Segment pooling: pooled[batch[n]] += agg2[n]; counts[batch[n]] += 1
// ---------------------------------------------------------------------------
__global__ void pool_kernel(const int* __restrict__ batch) {
    int t = blockIdx.x * blockDim.x + threadIdx.x;
    if (t >= N_NODES * 16) return;
    int n = t >> 4, c = t & 15;
    int g = batch[n];
    float4 v = ((const float4*)g_agg2)[n * 16 + c];
    atomicAdd(&((float4*)g_pooled)[g * 16 + c], v);
    if (c == 0) atomicAdd(&g_counts[g], 1.0f);
}

// ---------------------------------------------------------------------------
// Final FC + sigmoid
// ---------------------------------------------------------------------------
__global__ void final_kernel(const float* __restrict__ Wfc,
                             float* __restrict__ out) {
    __shared__ float wf[DIM];
    int tid = threadIdx.x;
    if (tid < DIM) wf[tid] = Wfc[tid];
    __syncthreads();
    if (tid >= N_GRAPHS) return;
    float cnt = fmaxf(g_counts[tid], 1.0f);
    float s = 0.f;
    #pragma unroll
    for (int d = 0; d < DIM; d++)
        s += g_pooled[tid * DIM + d] * wf[d];
    s /= cnt;
    out[tid] = 1.0f / (1.0f + expf(-s));
}

// ---------------------------------------------------------------------------
extern "C" void kernel_launch(void* const* d_in, const int* in_sizes, int n_in,
                              void* d_out, int out_size) {
    const float* x    = (const float*)d_in[0];
    const int*   ei   = (const int*)d_in[1];
    const int*   batch= (const int*)d_in[2];
    const float* W1   = (const float*)d_in[3];
    const float* W2   = (const float*)d_in[4];
    const float* Wfc  = (const float*)d_in[5];
    float*       out  = (float*)d_out;

    zero_kernel<<<(N_NODES + 255) / 256, 256>>>();
    hist_kernel<<<(N_EDGES + 255) / 256, 256>>>(ei);
    scan_kernel<<<1, 1024>>>();
    fill_kernel<<<(N_EDGES + 255) / 256, 256>>>(ei);

    gemm_kernel<N_FEAT, true><<<(N_NODES + 127) / 128, 256>>>((const float4*)x, W1);
    gather_kernel<<<(N_NODES * 16) / 256, 256>>>(0);
    gemm_kernel<DIM, false><<<(N_NODES + 127) / 128, 256>>>((const float4*)x, W2);
    gather_kernel<<<(N_NODES * 16) / 256, 256>>>(1);

    pool_kernel<<<(N_NODES * 16) / 256, 256>>>(batch);
    final_kernel<<<1, N_GRAPHS>>>(Wfc, out);
}

// round 6
// speedup vs baseline: 1.8197x; 1.8197x over previous
#include <cuda_runtime.h>
#include <cuda_bf16.h>

// Problem constants (match reference)
#define N_NODES 50000
#define N_EDGES 800000
#define N_FEAT  128
#define DIM     64
#define N_GRAPHS 512
#define SCAN_BLOCKS ((N_NODES + 255) / 256)   // 196

// Scratch (device globals — no allocation allowed)
__device__ __align__(16) float g_h[N_NODES * DIM];      // gemm1 output
__device__ __align__(16) float g_agg1[N_NODES * DIM];   // relu(A @ h1)
__device__ __align__(16) float g_pooled[N_GRAPHS * DIM];
__device__ __align__(16) float g_counts[N_GRAPHS];
// CSR (by destination)
__device__ __align__(16) int g_deg[N_NODES];
__device__ int g_off[N_NODES + 1];
__device__ int g_cursor[N_NODES];
__device__ int g_csr[N_EDGES];
__device__ int g_bsum[SCAN_BLOCKS];
__device__ int g_bbase[SCAN_BLOCKS];

// ---------------------------------------------------------------------------
// Zero small state
// ---------------------------------------------------------------------------
__global__ void zero_kernel() {
    int i = blockIdx.x * blockDim.x + threadIdx.x;
    if (i < N_NODES) g_deg[i] = 0;
    if (i < N_GRAPHS * (DIM / 4))
        ((float4*)g_pooled)[i] = make_float4(0.f, 0.f, 0.f, 0.f);
    if (i < N_GRAPHS) g_counts[i] = 0.f;
    if (i == 0) g_off[N_NODES] = N_EDGES;   // known total
}

// ---------------------------------------------------------------------------
// CSR build: int4 histogram, hierarchical scan, int4 atomic-bump fill
// ---------------------------------------------------------------------------
__global__ void hist_kernel(const int* __restrict__ ei) {
    int t = blockIdx.x * blockDim.x + threadIdx.x;
    if (t >= N_EDGES / 4) return;
    int4 d = ((const int4*)(ei + N_EDGES))[t];
    atomicAdd(&g_deg[d.x], 1);
    atomicAdd(&g_deg[d.y], 1);
    atomicAdd(&g_deg[d.z], 1);
    atomicAdd(&g_deg[d.w], 1);
}

// block sums of deg
__global__ void scan_sums_kernel() {
    __shared__ int sd[256];
    int tid = threadIdx.x;
    int i = blockIdx.x * 256 + tid;
    sd[tid] = (i < N_NODES) ? g_deg[i] : 0;
    __syncthreads();
    for (int s = 128; s > 0; s >>= 1) {
        if (tid < s) sd[tid] += sd[tid + s];
        __syncthreads();
    }
    if (tid == 0) g_bsum[blockIdx.x] = sd[0];
}

// exclusive scan of the 196 block sums (single block, 256 threads)
__global__ void scan_base_kernel() {
    __shared__ int sd[256];
    int tid = threadIdx.x;
    sd[tid] = (tid < SCAN_BLOCKS) ? g_bsum[tid] : 0;
    __syncthreads();
    for (int off = 1; off < 256; off <<= 1) {
        int v = (tid >= off) ? sd[tid - off] : 0;
        __syncthreads();
        sd[tid] += v;
        __syncthreads();
    }
    if (tid < SCAN_BLOCKS)
        g_bbase[tid] = sd[tid] - g_bsum[tid];   // exclusive
}

// per-block exclusive scan (shuffle) + base -> g_off, g_cursor
__global__ void scan_final_kernel() {
    __shared__ int wsum[8];
    int tid = threadIdx.x;
    int i = blockIdx.x * 256 + tid;
    int v = (i < N_NODES) ? g_deg[i] : 0;
    int lane = tid & 31, wid = tid >> 5;
    // warp inclusive scan
    int inc = v;
    #pragma unroll
    for (int off = 1; off < 32; off <<= 1) {
        int u = __shfl_up_sync(0xffffffff, inc, off);
        if (lane >= off) inc += u;
    }
    if (lane == 31) wsum[wid] = inc;
    __syncthreads();
    if (wid == 0) {
        int w = (lane < 8) ? wsum[lane] : 0;
        #pragma unroll
        for (int off = 1; off < 8; off <<= 1) {
            int u = __shfl_up_sync(0xffffffff, w, off);
            if (lane >= off) w += u;
        }
        if (lane < 8) wsum[lane] = w;
    }
    __syncthreads();
    int warpBase = (wid == 0) ? 0 : wsum[wid - 1];
    int excl = g_bbase[blockIdx.x] + warpBase + inc - v;
    if (i < N_NODES) {
        g_off[i] = excl;
        g_cursor[i] = excl;
    }
}

__global__ void fill_kernel(const int* __restrict__ ei) {
    int t = blockIdx.x * blockDim.x + threadIdx.x;
    if (t >= N_EDGES / 4) return;
    int4 s = ((const int4*)ei)[t];
    int4 d = ((const int4*)(ei + N_EDGES))[t];
    int p0 = atomicAdd(&g_cursor[d.x], 1);
    int p1 = atomicAdd(&g_cursor[d.y], 1);
    int p2 = atomicAdd(&g_cursor[d.z], 1);
    int p3 = atomicAdd(&g_cursor[d.w], 1);
    g_csr[p0] = s.x; g_csr[p1] = s.y; g_csr[p2] = s.z; g_csr[p3] = s.w;
}

// ---------------------------------------------------------------------------
// GEMM1: g_h[N,64] = x[N,128] @ W1[128,64], packed fma.rn.f32x2.
// Block = 256 threads / 128 rows; thread: 4 rows x 8 cols.
// ---------------------------------------------------------------------------
typedef unsigned long long u64;

__global__ void gemm1_kernel(const float4* __restrict__ xin,
                             const float* __restrict__ W) {
    constexpr int K = N_FEAT;
    constexpr int NC4 = K / 4;
    constexpr int CHUNK = 16;
    constexpr int NCHUNK = K / CHUNK;
    __shared__ __align__(16) float Ws[K * 64];
    __shared__ __align__(16) float xs[128 * 20];

    int tid = threadIdx.x;
    for (int i = tid; i < K * 16; i += 256)
        ((float4*)Ws)[i] = ((const float4*)W)[i];

    int rowBase = blockIdx.x * 128;
    int q  = tid >> 3;
    int cg = tid & 7;

    u64 acc[4][4];
    #pragma unroll
    for (int i = 0; i < 4; i++)
        #pragma unroll
        for (int j = 0; j < 4; j++) acc[i][j] = 0ULL;

    for (int ch = 0; ch < NCHUNK; ch++) {
        __syncthreads();
        for (int l = tid; l < 512; l += 256) {
            int r = l >> 2, j = l & 3;
            int gr = rowBase + r;
            float4 v = make_float4(0.f, 0.f, 0.f, 0.f);
            if (gr < N_NODES) v = xin[gr * NC4 + ch * 4 + j];
            *(float4*)&xs[r * 20 + j * 4] = v;
        }
        __syncthreads();

        #pragma unroll
        for (int k4 = 0; k4 < CHUNK / 4; k4++) {
            float4 xv[4];
            #pragma unroll
            for (int i = 0; i < 4; i++)
                xv[i] = *(const float4*)&xs[(q + 32 * i) * 20 + k4 * 4];
            #pragma unroll
            for (int kk = 0; kk < 4; kk++) {
                int k = ch * CHUNK + k4 * 4 + kk;
                const double2* Wp = (const double2*)&Ws[k * 64 + cg * 8];
                double2 wA = Wp[0], wB = Wp[1];
                u64 w0 = __double_as_longlong(wA.x);
                u64 w1 = __double_as_longlong(wA.y);
                u64 w2 = __double_as_longlong(wB.x);
                u64 w3 = __double_as_longlong(wB.y);
                #pragma unroll
                for (int i = 0; i < 4; i++) {
                    float xf = (kk == 0) ? xv[i].x : (kk == 1) ? xv[i].y
                             : (kk == 2) ? xv[i].z : xv[i].w;
                    u64 xp;
                    asm("mov.b64 %0, {%1, %2};" : "=l"(xp) : "f"(xf), "f"(xf));
                    asm("fma.rn.f32x2 %0, %1, %2, %0;" : "+l"(acc[i][0]) : "l"(xp), "l"(w0));
                    asm("fma.rn.f32x2 %0, %1, %2, %0;" : "+l"(acc[i][1]) : "l"(xp), "l"(w1));
                    asm("fma.rn.f32x2 %0, %1, %2, %0;" : "+l"(acc[i][2]) : "l"(xp), "l"(w2));
                    asm("fma.rn.f32x2 %0, %1, %2, %0;" : "+l"(acc[i][3]) : "l"(xp), "l"(w3));
                }
            }
        }
    }

    #pragma unroll
    for (int i = 0; i < 4; i++) {
        int r = rowBase + q + 32 * i;
        if (r < N_NODES) {
            float4 o0, o1;
            asm("mov.b64 {%0, %1}, %2;" : "=f"(o0.x), "=f"(o0.y) : "l"(acc[i][0]));
            asm("mov.b64 {%0, %1}, %2;" : "=f"(o0.z), "=f"(o0.w) : "l"(acc[i][1]));
            asm("mov.b64 {%0, %1}, %2;" : "=f"(o1.x), "=f"(o1.y) : "l"(acc[i][2]));
            asm("mov.b64 {%0, %1}, %2;" : "=f"(o1.z), "=f"(o1.w) : "l"(acc[i][3]));
            ((float4*)g_h)[r * 16 + cg * 2]     = o0;
            ((float4*)g_h)[r * 16 + cg * 2 + 1] = o1;
        }
    }
}

// ---------------------------------------------------------------------------
// Gather 1: agg1[n] = relu( sum_{s in CSR[n]} h[s] ). 16 lanes/node, 4-way MLP.
// ---------------------------------------------------------------------------
__global__ void gather1_kernel() {
    const float4* h = (const float4*)g_h;
    float4* agg = (float4*)g_agg1;
    int t = blockIdx.x * blockDim.x + threadIdx.x;
    if (t >= N_NODES * 16) return;
    int n = t >> 4, c = t & 15;
    int b = g_off[n], e = g_off[n + 1];
    float4 acc = make_float4(0.f, 0.f, 0.f, 0.f);
    int i = b;
    for (; i + 3 < e; i += 4) {
        int s0 = g_csr[i], s1 = g_csr[i+1], s2 = g_csr[i+2], s3 = g_csr[i+3];
        float4 v0 = h[s0 * 16 + c];
        float4 v1 = h[s1 * 16 + c];
        float4 v2 = h[s2 * 16 + c];
        float4 v3 = h[s3 * 16 + c];
        acc.x += v0.x + v1.x + v2.x + v3.x;
        acc.y += v0.y + v1.y + v2.y + v3.y;
        acc.z += v0.z + v1.z + v2.z + v3.z;
        acc.w += v0.w + v1.w + v2.w + v3.w;
    }
    for (; i < e; i++) {
        int s = g_csr[i];
        float4 v = h[s * 16 + c];
        acc.x += v.x; acc.y += v.y; acc.z += v.z; acc.w += v.w;
    }
    acc.x = fmaxf(acc.x, 0.f); acc.y = fmaxf(acc.y, 0.f);
    acc.z = fmaxf(acc.z, 0.f); acc.w = fmaxf(acc.w, 0.f);
    agg[n * 16 + c] = acc;
}

// ---------------------------------------------------------------------------
// Gather 2 fused with pooling (GEMM2 moved after pooling algebraically):
// pooled[batch[n]] += sum_{s in CSR[n]} agg1[s]; counts[batch[n]] += 1.
// ---------------------------------------------------------------------------
__global__ void gather2_pool_kernel(const int* __restrict__ batch) {
    const float4* h = (const float4*)g_agg1;
    int t = blockIdx.x * blockDim.x + threadIdx.x;
    if (t >= N_NODES * 16) return;
    int n = t >> 4, c = t & 15;
    int b = g_off[n], e = g_off[n + 1];
    float4 acc = make_float4(0.f, 0.f, 0.f, 0.f);
    int i = b;
    for (; i + 3 < e; i += 4) {
        int s0 = g_csr[i], s1 = g_csr[i+1], s2 = g_csr[i+2], s3 = g_csr[i+3];
        float4 v0 = h[s0 * 16 + c];
        float4 v1 = h[s1 * 16 + c];
        float4 v2 = h[s2 * 16 + c];
        float4 v3 = h[s3 * 16 + c];
        acc.x += v0.x + v1.x + v2.x + v3.x;
        acc.y += v0.y + v1.y + v2.y + v3.y;
        acc.z += v0.z + v1.z + v2.z + v3.z;
        acc.w += v0.w + v1.w + v2.w + v3.w;
    }
    for (; i < e; i++) {
        int s = g_csr[i];
        float4 v = h[s * 16 + c];
        acc.x += v.x; acc.y += v.y; acc.z += v.z; acc.w += v.w;
    }
    int g = batch[n];
    atomicAdd(&((float4*)g_pooled)[g * 16 + c], acc);
    if (c == 0) atomicAdd(&g_counts[g], 1.0f);
}

// ---------------------------------------------------------------------------
// Final: wv = W2 @ Wfc (64), out[g] = sigmoid( dot(pooled[g], wv) / cnt[g] )
// ---------------------------------------------------------------------------
__global__ void final_kernel(const float* __restrict__ W2,
                             const float* __restrict__ Wfc,
                             float* __restrict__ out) {
    __shared__ float wv[DIM];
    int tid = threadIdx.x;
    if (tid < DIM) {
        float s = 0.f;
        #pragma unroll
        for (int d = 0; d < DIM; d++)
            s += W2[tid * DIM + d] * Wfc[d];
        wv[tid] = s;
    }
    __syncthreads();
    if (tid >= N_GRAPHS) return;
    float cnt = fmaxf(g_counts[tid], 1.0f);
    float s = 0.f;
    #pragma unroll
    for (int d = 0; d < DIM; d++)
        s += g_pooled[tid * DIM + d] * wv[d];
    s /= cnt;
    out[tid] = 1.0f / (1.0f + expf(-s));
}

// ---------------------------------------------------------------------------
extern "C" void kernel_launch(void* const* d_in, const int* in_sizes, int n_in,
                              void* d_out, int out_size) {
    const float* x    = (const float*)d_in[0];
    const int*   ei   = (const int*)d_in[1];
    const int*   batch= (const int*)d_in[2];
    const float* W1   = (const float*)d_in[3];
    const float* W2   = (const float*)d_in[4];
    const float* Wfc  = (const float*)d_in[5];
    float*       out  = (float*)d_out;

    zero_kernel<<<(N_NODES + 255) / 256, 256>>>();
    hist_kernel<<<(N_EDGES / 4 + 255) / 256, 256>>>(ei);
    scan_sums_kernel<<<SCAN_BLOCKS, 256>>>();
    scan_base_kernel<<<1, 256>>>();
    scan_final_kernel<<<SCAN_BLOCKS, 256>>>();
    fill_kernel<<<(N_EDGES / 4 + 255) / 256, 256>>>(ei);

    gemm1_kernel<<<(N_NODES + 127) / 128, 256>>>((const float4*)x, W1);
    gather1_kernel<<<(N_NODES * 16) / 256, 256>>>();
    gather2_pool_kernel<<<(N_NODES * 16) / 256, 256>>>(batch);

    final_kernel<<<1, N_GRAPHS>>>(W2, Wfc, out);
}